// round 1
// baseline (speedup 1.0000x reference)
#include <cuda_runtime.h>
#include <math.h>

// Problem constants
#define NROWS 30000
#define HH    8
#define SD    17          // OT+1
#define OSD   240
#define DD    257         // IN_DIM == OUT_DIM
#define FF    2056        // H * 257

// ---------------- scratch (device globals; no runtime alloc allowed) -------
__device__ float g_Yq[NROWS * FF];      // phiQ after epilogue
__device__ float g_Yk[NROWS * FF];      // phiK after epilogue
__device__ float g_Yv[NROWS * FF];      // V after epilogue
__device__ float g_ktv[HH * DD * DD];   // block-diagonal masked
__device__ float g_sumK[FF];            // per (h, m) column sums of phiK
__device__ float g_denS[NROWS * HH];
__device__ float g_denH[NROWS * HH];
__device__ float g_cs[NROWS * HH * SD];   // N x 136
__device__ float g_ch[NROWS * HH * OSD];  // N x 1920
__device__ float g_atts[NROWS * SD];
__device__ float g_b[NROWS * OSD];

// ---------------- generic NT SGEMM: C[m,n] = sum_k A[m,k]*B[n,k] ----------
__global__ __launch_bounds__(256) void sgemm_nt(
    const float* __restrict__ A, const float* __restrict__ B,
    float* __restrict__ C, int M, int Nc, int K, int lda, int ldb, int ldc)
{
    const int BM = 128, BN = 128, BK = 16;
    __shared__ float As[BK][BM + 1];
    __shared__ float Bs[BK][BN + 1];
    int tid = threadIdx.x;
    int row0 = blockIdx.y * BM;
    int col0 = blockIdx.x * BN;
    int ty = tid >> 4, tx = tid & 15;

    float acc[8][8];
#pragma unroll
    for (int i = 0; i < 8; i++)
#pragma unroll
        for (int j = 0; j < 8; j++) acc[i][j] = 0.f;

    for (int k0 = 0; k0 < K; k0 += BK) {
#pragma unroll
        for (int i = 0; i < 8; i++) {
            int idx = tid + i * 256;
            int m = idx >> 4, k = idx & 15;
            int gm = row0 + m, gk = k0 + k;
            As[k][m] = (gm < M && gk < K) ? A[gm * lda + gk] : 0.f;
        }
#pragma unroll
        for (int i = 0; i < 8; i++) {
            int idx = tid + i * 256;
            int n = idx >> 4, k = idx & 15;
            int gn = col0 + n, gk = k0 + k;
            Bs[k][n] = (gn < Nc && gk < K) ? B[gn * ldb + gk] : 0.f;
        }
        __syncthreads();
#pragma unroll
        for (int k = 0; k < BK; k++) {
            float af[8], bf[8];
#pragma unroll
            for (int i = 0; i < 8; i++) af[i] = As[k][ty * 8 + i];
#pragma unroll
            for (int j = 0; j < 8; j++) bf[j] = Bs[k][tx * 8 + j];
#pragma unroll
            for (int i = 0; i < 8; i++)
#pragma unroll
                for (int j = 0; j < 8; j++) acc[i][j] += af[i] * bf[j];
        }
        __syncthreads();
    }
#pragma unroll
    for (int i = 0; i < 8; i++) {
        int gm = row0 + ty * 8 + i;
        if (gm >= M) continue;
#pragma unroll
        for (int j = 0; j < 8; j++) {
            int gn = col0 + tx * 8 + j;
            if (gn < Nc) C[gm * ldc + gn] = acc[i][j];
        }
    }
}

// --------- pseudo-linear epilogue: normalize first 17, optional phi --------
__global__ void ep1_kernel(float* __restrict__ Y, int do_phi)
{
    int warp = (blockIdx.x * blockDim.x + threadIdx.x) >> 5;
    int lane = threadIdx.x & 31;
    if (warp >= NROWS * HH) return;
    int n = warp / HH, h = warp % HH;
    float* p = Y + n * FF + h * DD;

    float x = (lane < SD) ? p[lane] : 0.f;
    float ss = x * x;
#pragma unroll
    for (int o = 16; o > 0; o >>= 1) ss += __shfl_xor_sync(0xffffffffu, ss, o);
    float scale = 1.f / (sqrtf(ss) + 1e-8f);
    if (lane < SD) {
        float y = x * scale;
        if (do_phi) y = (y > 0.f) ? y + 1.f : expf(y);
        p[lane] = y;
    }
    if (do_phi) {
        for (int j = SD + lane; j < DD; j += 32) {
            float y = p[j];
            p[j] = (y > 0.f) ? y + 1.f : expf(y);
        }
    }
}

__global__ void zero_kernel(float* __restrict__ p, int n)
{
    int i = blockIdx.x * blockDim.x + threadIdx.x;
    if (i < n) p[i] = 0.f;
}

// --------- column sums of phiK: sumK[f] = sum_n phiK[n, f] ----------------
__global__ void colsum_kernel(const float* __restrict__ Y, float* __restrict__ out)
{
    int f = blockIdx.x * blockDim.x + threadIdx.x;
    if (f >= FF) return;
    int n0 = blockIdx.y * 750;
    int n1 = n0 + 750; if (n1 > NROWS) n1 = NROWS;
    float s = 0.f;
    for (int n = n0; n < n1; n++) s += Y[n * FF + f];
    atomicAdd(&out[f], s);
}

// --------- ktv[h] = phiK_h^T @ V_h  (split-K over N, diag-block masked) ----
__global__ __launch_bounds__(256) void ktv_kernel(
    const float* __restrict__ PK, const float* __restrict__ V,
    float* __restrict__ ktv, int nsplit)
{
    const int BT = 64, BK = 16;
    __shared__ float As[BK][BT];
    __shared__ float Bs[BK][BT];
    int h  = blockIdx.z / nsplit;
    int sp = blockIdx.z % nsplit;
    int m0 = blockIdx.x * BT;
    int d0 = blockIdx.y * BT;
    int chunk = (NROWS + nsplit - 1) / nsplit;
    int n0 = sp * chunk;
    int n1 = n0 + chunk; if (n1 > NROWS) n1 = NROWS;
    int tid = threadIdx.x, ty = tid >> 4, tx = tid & 15;
    float acc[4][4];
#pragma unroll
    for (int i = 0; i < 4; i++)
#pragma unroll
        for (int j = 0; j < 4; j++) acc[i][j] = 0.f;

    const float* pk = PK + h * DD;
    const float* pv = V  + h * DD;
    for (int k0 = n0; k0 < n1; k0 += BK) {
#pragma unroll
        for (int i = 0; i < 4; i++) {
            int idx = tid + i * 256;
            int k = idx >> 6, m = idx & 63;
            int gn = k0 + k;
            bool ok = (gn < n1);
            As[k][m] = (ok && m0 + m < DD) ? pk[gn * FF + m0 + m] : 0.f;
            Bs[k][m] = (ok && d0 + m < DD) ? pv[gn * FF + d0 + m] : 0.f;
        }
        __syncthreads();
#pragma unroll
        for (int k = 0; k < BK; k++) {
            float af[4], bf[4];
#pragma unroll
            for (int i = 0; i < 4; i++) af[i] = As[k][ty * 4 + i];
#pragma unroll
            for (int j = 0; j < 4; j++) bf[j] = Bs[k][tx * 4 + j];
#pragma unroll
            for (int i = 0; i < 4; i++)
#pragma unroll
                for (int j = 0; j < 4; j++) acc[i][j] += af[i] * bf[j];
        }
        __syncthreads();
    }
    float* kt = ktv + h * DD * DD;
#pragma unroll
    for (int i = 0; i < 4; i++) {
        int m = m0 + ty * 4 + i;
        if (m >= DD) continue;
#pragma unroll
        for (int j = 0; j < 4; j++) {
            int d = d0 + tx * 4 + j;
            if (d >= DD) continue;
            if ((m < SD) != (d < SD)) continue;  // keep diagonal blocks only
            atomicAdd(&kt[m * DD + d], acc[i][j]);
        }
    }
}

// --------- den_s / den_h per (n,h) -----------------------------------------
__global__ void den_kernel(const float* __restrict__ PQ,
                           const float* __restrict__ sumK,
                           float* __restrict__ dS, float* __restrict__ dH)
{
    int n = blockIdx.x;
    int h = threadIdx.x >> 5;
    int lane = threadIdx.x & 31;
    const float* p = PQ + n * FF + h * DD;
    const float* s = sumK + h * DD;
    float as = 0.f, ah = 0.f;
    for (int m = lane; m < DD; m += 32) {
        float v = p[m] * s[m];
        if (m < SD) as += v; else ah += v;
    }
#pragma unroll
    for (int o = 16; o > 0; o >>= 1) {
        as += __shfl_xor_sync(0xffffffffu, as, o);
        ah += __shfl_xor_sync(0xffffffffu, ah, o);
    }
    if (lane == 0) { dS[n * HH + h] = as; dH[n * HH + h] = ah; }
}

// --------- c = (phiQ @ ktv) / den, scattered into c_s / c_h ----------------
__global__ __launch_bounds__(256) void cgemm_kernel(
    const float* __restrict__ PQ, const float* __restrict__ ktv,
    const float* __restrict__ dS, const float* __restrict__ dH,
    float* __restrict__ cs, float* __restrict__ ch)
{
    const int BM = 128, BN = 64, BK = 16;
    __shared__ float As[BK][BM + 1];
    __shared__ float Bs[BK][BN];
    int h  = blockIdx.z;
    int n0 = blockIdx.y * BM;
    int d0 = blockIdx.x * BN;
    int tid = threadIdx.x, ty = tid >> 4, tx = tid & 15;
    float acc[8][4];
#pragma unroll
    for (int i = 0; i < 8; i++)
#pragma unroll
        for (int j = 0; j < 4; j++) acc[i][j] = 0.f;

    const float* Ap = PQ + h * DD;
    const float* Bp = ktv + h * DD * DD;
    for (int k0 = 0; k0 < DD; k0 += BK) {
#pragma unroll
        for (int i = 0; i < 8; i++) {
            int idx = tid + i * 256;
            int m = idx >> 4, k = idx & 15;
            As[k][m] = (n0 + m < NROWS && k0 + k < DD) ? Ap[(n0 + m) * FF + k0 + k] : 0.f;
        }
#pragma unroll
        for (int i = 0; i < 4; i++) {
            int idx = tid + i * 256;
            int k = idx >> 6, d = idx & 63;
            Bs[k][d] = (k0 + k < DD && d0 + d < DD) ? Bp[(k0 + k) * DD + d0 + d] : 0.f;
        }
        __syncthreads();
#pragma unroll
        for (int k = 0; k < BK; k++) {
            float af[8], bf[4];
#pragma unroll
            for (int i = 0; i < 8; i++) af[i] = As[k][ty * 8 + i];
#pragma unroll
            for (int j = 0; j < 4; j++) bf[j] = Bs[k][tx * 4 + j];
#pragma unroll
            for (int i = 0; i < 8; i++)
#pragma unroll
                for (int j = 0; j < 4; j++) acc[i][j] += af[i] * bf[j];
        }
        __syncthreads();
    }
#pragma unroll
    for (int i = 0; i < 8; i++) {
        int n = n0 + ty * 8 + i;
        if (n >= NROWS) continue;
        float ds = dS[n * HH + h] + 1e-6f;
        float dh = dH[n * HH + h] + 1e-8f;
#pragma unroll
        for (int j = 0; j < 4; j++) {
            int d = d0 + tx * 4 + j;
            if (d >= DD) continue;
            if (d < SD) cs[n * (HH * SD) + h * SD + d] = acc[i][j] / ds;
            else        ch[n * (HH * OSD) + h * OSD + (d - SD)] = acc[i][j] / dh;
        }
    }
}

// --------- a = c_s @ Ws^T, then att_s = a / max(||a||, 1e-12) --------------
__global__ void a_kernel(const float* __restrict__ cs,
                         const float* __restrict__ Ws,
                         float* __restrict__ atts)
{
    __shared__ float ws[SD * 136];
    for (int i = threadIdx.x; i < SD * 136; i += blockDim.x) ws[i] = Ws[i];
    __syncthreads();
    int warp = threadIdx.x >> 5, lane = threadIdx.x & 31;
    int n = blockIdx.x * 8 + warp;
    if (n >= NROWS) return;
    float acc[SD];
#pragma unroll
    for (int o = 0; o < SD; o++) acc[o] = 0.f;
    for (int f = lane; f < 136; f += 32) {
        float x = cs[n * 136 + f];
#pragma unroll
        for (int o = 0; o < SD; o++) acc[o] += x * ws[o * 136 + f];
    }
#pragma unroll
    for (int o = 0; o < SD; o++)
#pragma unroll
        for (int s = 16; s > 0; s >>= 1)
            acc[o] += __shfl_xor_sync(0xffffffffu, acc[o], s);
    if (lane == 0) {
        float ss = 0.f;
#pragma unroll
        for (int o = 0; o < SD; o++) ss += acc[o] * acc[o];
        float sc = 1.f / fmaxf(sqrtf(ss), 1e-12f);
#pragma unroll
        for (int o = 0; o < SD; o++) atts[n * SD + o] = acc[o] * sc;
    }
}

// --------- final epilogue: b-norm clamp + bt, assemble output --------------
__global__ void final_kernel(const float* __restrict__ b,
                             const float* __restrict__ atts,
                             float* __restrict__ out)
{
    int warp = threadIdx.x >> 5, lane = threadIdx.x & 31;
    int n = blockIdx.x * 8 + warp;
    if (n >= NROWS) return;
    const float* br = b + n * OSD;
    float ss = 0.f;
    for (int j = lane; j < OSD; j += 32) { float v = br[j]; ss += v * v; }
#pragma unroll
    for (int s = 16; s > 0; s >>= 1) ss += __shfl_xor_sync(0xffffffffu, ss, s);
    float nr  = sqrtf(ss);
    float bn  = nr + 1e-8f;
    float bnc = fminf(bn, 1e6f);
    float bt  = sqrtf(bnc * bnc + 1.0f);
    float scale = (bn > 1e6f) ? (1e6f / fmaxf(nr, 1e-12f * bnc)) : 1.0f;
    float* o = out + n * DD;
    for (int j = lane; j < OSD; j += 32) o[SD + j] = br[j] * scale;
    if (lane < SD) o[lane] = bt * atts[n * SD + lane];
}

// ---------------------------------------------------------------------------
extern "C" void kernel_launch(void* const* d_in, const int* in_sizes, int n_in,
                              void* d_out, int out_size)
{
    const float* qin = (const float*)d_in[0];
    const float* sin = (const float*)d_in[1];
    const float* Wq  = (const float*)d_in[2];
    const float* Wk  = (const float*)d_in[3];
    const float* Wv  = (const float*)d_in[4];
    const float* Ws  = (const float*)d_in[5];
    const float* Wh  = (const float*)d_in[6];
    float* out = (float*)d_out;

    float *Yq, *Yk, *Yv, *ktv, *sumK, *dS, *dH, *cs, *ch, *atts, *bb;
    cudaGetSymbolAddress((void**)&Yq,   g_Yq);
    cudaGetSymbolAddress((void**)&Yk,   g_Yk);
    cudaGetSymbolAddress((void**)&Yv,   g_Yv);
    cudaGetSymbolAddress((void**)&ktv,  g_ktv);
    cudaGetSymbolAddress((void**)&sumK, g_sumK);
    cudaGetSymbolAddress((void**)&dS,   g_denS);
    cudaGetSymbolAddress((void**)&dH,   g_denH);
    cudaGetSymbolAddress((void**)&cs,   g_cs);
    cudaGetSymbolAddress((void**)&ch,   g_ch);
    cudaGetSymbolAddress((void**)&atts, g_atts);
    cudaGetSymbolAddress((void**)&bb,   g_b);

    const int rowTiles = (NROWS + 127) / 128;   // 235
    const int fTiles   = (FF + 127) / 128;      // 17

    // 1. projections: Y = X @ W^T  (NT)
    sgemm_nt<<<dim3(fTiles, rowTiles), 256>>>(qin, Wq, Yq, NROWS, FF, DD, DD, DD, FF);
    sgemm_nt<<<dim3(fTiles, rowTiles), 256>>>(sin, Wk, Yk, NROWS, FF, DD, DD, DD, FF);
    sgemm_nt<<<dim3(fTiles, rowTiles), 256>>>(sin, Wv, Yv, NROWS, FF, DD, DD, DD, FF);

    // 2. pseudo-linear normalization + phi
    ep1_kernel<<<NROWS, 256>>>(Yq, 1);
    ep1_kernel<<<NROWS, 256>>>(Yk, 1);
    ep1_kernel<<<NROWS, 256>>>(Yv, 0);

    // 3. zero accumulators
    zero_kernel<<<(HH * DD * DD + 255) / 256, 256>>>(ktv, HH * DD * DD);
    zero_kernel<<<(FF + 255) / 256, 256>>>(sumK, FF);

    // 4. sumK and ktv (split-K with atomics)
    colsum_kernel<<<dim3((FF + 255) / 256, 40), 256>>>(Yk, sumK);
    const int nsplit = 10;
    ktv_kernel<<<dim3(5, 5, HH * nsplit), 256>>>(Yk, Yv, ktv, nsplit);

    // 5. denominators
    den_kernel<<<NROWS, 256>>>(Yq, sumK, dS, dH);

    // 6. c = (phiQ @ ktv) / den, scattered into c_s / c_h
    cgemm_kernel<<<dim3(5, rowTiles, HH), 256>>>(Yq, ktv, dS, dH, cs, ch);

    // 7. small Ws GEMM + att_s normalize
    a_kernel<<<(NROWS + 7) / 8, 256>>>(cs, Ws, atts);

    // 8. b = c_h @ Wh^T  (NT)
    sgemm_nt<<<dim3(2, rowTiles), 256>>>(ch, Wh, bb, NROWS, OSD, HH * OSD, HH * OSD, HH * OSD, OSD);

    // 9. final epilogue
    final_kernel<<<(NROWS + 7) / 8, 256>>>(bb, atts, out);
}

// round 2
// speedup vs baseline: 2.0938x; 2.0938x over previous
#include <cuda_runtime.h>
#include <cuda_bf16.h>
#include <stdint.h>
#include <math.h>

// Problem constants
#define NROWS 30000
#define HH    8
#define SD    17          // OT+1
#define OSD   240
#define DD    257         // IN_DIM == OUT_DIM
#define FF    2056        // H * 257

// ---------------- scratch (device globals; no runtime alloc allowed) -------
__device__ float g_Yq[NROWS * FF];      // phiQ after epilogue
__device__ float g_Yk[NROWS * FF];      // phiK after epilogue
__device__ float g_Yv[NROWS * FF];      // V after epilogue
__device__ float g_ktvT[HH * DD * DD];  // TRANSPOSED: ktvT[h][d][m]
__device__ float g_sumK[FF];
__device__ float g_denS[NROWS * HH];
__device__ float g_denH[NROWS * HH];
__device__ float g_cs[NROWS * HH * SD];   // N x 136
__device__ float g_ch[NROWS * HH * OSD];  // N x 1920
__device__ float g_atts[NROWS * SD];
__device__ float g_b[NROWS * OSD];

// ---------------------------------------------------------------------------
// helpers
// ---------------------------------------------------------------------------
__device__ __forceinline__ void mma16816(float c[4], const uint32_t a[4], const uint32_t b[2])
{
    asm volatile(
        "mma.sync.aligned.m16n8k16.row.col.f32.bf16.bf16.f32 "
        "{%0,%1,%2,%3}, {%4,%5,%6,%7}, {%8,%9}, {%0,%1,%2,%3};\n"
        : "+f"(c[0]), "+f"(c[1]), "+f"(c[2]), "+f"(c[3])
        : "r"(a[0]), "r"(a[1]), "r"(a[2]), "r"(a[3]), "r"(b[0]), "r"(b[1]));
}

__device__ __forceinline__ void cvt_pack(float x0, float x1, uint32_t& hp, uint32_t& lp)
{
    __nv_bfloat16 h0 = __float2bfloat16(x0);
    __nv_bfloat16 h1 = __float2bfloat16(x1);
    __nv_bfloat16 l0 = __float2bfloat16(x0 - __bfloat162float(h0));
    __nv_bfloat16 l1 = __float2bfloat16(x1 - __bfloat162float(h1));
    __nv_bfloat162 hh; hh.x = h0; hh.y = h1;
    __nv_bfloat162 ll; ll.x = l0; ll.y = l1;
    hp = *reinterpret_cast<uint32_t*>(&hh);
    lp = *reinterpret_cast<uint32_t*>(&ll);
}

// ---------------------------------------------------------------------------
// Generic NT tensor-core GEMM with bf16 hi/lo split:
//   C[m,n] = sum_k A[m,k]*B[n,k],  A,B,C fp32 in gmem.
// epi==0: plain store to C.
// epi==1: attention scatter: m=n-row, n=d; divide by den and write cs/ch.
// blockIdx.z selects batch (head); pointers advance by strides.
// ---------------------------------------------------------------------------
__global__ __launch_bounds__(256) void gemm_bf16s_nt(
    const float* __restrict__ A, const float* __restrict__ B, float* __restrict__ C,
    int M, int N, int K, int lda, int ldb, int ldc,
    int strideAz, int strideBz, int strideCz,
    int epi,
    const float* __restrict__ dS, const float* __restrict__ dH,
    float* __restrict__ cs, float* __restrict__ ch)
{
    __shared__ uint32_t Ah[128][20], Al[128][20], Bh[128][20], Bl[128][20];

    const int z = blockIdx.z;
    A += (long)z * strideAz;
    B += (long)z * strideBz;
    if (epi == 0) C += (long)z * strideCz;

    const int tid  = threadIdx.x;
    const int lane = tid & 31;
    const int wid  = tid >> 5;
    const int wm   = wid & 3;   // 4 warps along M (32 rows each)
    const int wn   = wid >> 2;  // 2 warps along N (64 cols each)
    const int row0 = blockIdx.y * 128;
    const int col0 = blockIdx.x * 128;
    const int r    = lane >> 2;
    const int q4   = lane & 3;

    float acc[2][8][4];
#pragma unroll
    for (int mt = 0; mt < 2; mt++)
#pragma unroll
        for (int nt = 0; nt < 8; nt++)
#pragma unroll
            for (int i = 0; i < 4; i++) acc[mt][nt][i] = 0.f;

    for (int k0 = 0; k0 < K; k0 += 32) {
        // fill A tile 128x32 (as 16 k-pairs)
#pragma unroll
        for (int i = 0; i < 8; i++) {
            int idx = tid + i * 256;
            int m = idx >> 4, kp = idx & 15;
            int gm = row0 + m, gk = k0 + kp * 2;
            float x0 = (gm < M && gk     < K) ? __ldg(&A[gm * lda + gk])     : 0.f;
            float x1 = (gm < M && gk + 1 < K) ? __ldg(&A[gm * lda + gk + 1]) : 0.f;
            uint32_t hp, lp; cvt_pack(x0, x1, hp, lp);
            Ah[m][kp] = hp; Al[m][kp] = lp;
        }
        // fill B tile 128x32
#pragma unroll
        for (int i = 0; i < 8; i++) {
            int idx = tid + i * 256;
            int n = idx >> 4, kp = idx & 15;
            int gn = col0 + n, gk = k0 + kp * 2;
            float x0 = (gn < N && gk     < K) ? __ldg(&B[gn * ldb + gk])     : 0.f;
            float x1 = (gn < N && gk + 1 < K) ? __ldg(&B[gn * ldb + gk + 1]) : 0.f;
            uint32_t hp, lp; cvt_pack(x0, x1, hp, lp);
            Bh[n][kp] = hp; Bl[n][kp] = lp;
        }
        __syncthreads();

#pragma unroll
        for (int ks = 0; ks < 2; ks++) {
            uint32_t ah[2][4], al[2][4];
#pragma unroll
            for (int mt = 0; mt < 2; mt++) {
                int m_ = wm * 32 + mt * 16;
                ah[mt][0] = Ah[m_ + r    ][ks * 8 + q4];
                ah[mt][1] = Ah[m_ + r + 8][ks * 8 + q4];
                ah[mt][2] = Ah[m_ + r    ][ks * 8 + 4 + q4];
                ah[mt][3] = Ah[m_ + r + 8][ks * 8 + 4 + q4];
                al[mt][0] = Al[m_ + r    ][ks * 8 + q4];
                al[mt][1] = Al[m_ + r + 8][ks * 8 + q4];
                al[mt][2] = Al[m_ + r    ][ks * 8 + 4 + q4];
                al[mt][3] = Al[m_ + r + 8][ks * 8 + 4 + q4];
            }
#pragma unroll
            for (int nt = 0; nt < 8; nt++) {
                int n_ = wn * 64 + nt * 8 + r;
                uint32_t bh[2], bl[2];
                bh[0] = Bh[n_][ks * 8 + q4];
                bh[1] = Bh[n_][ks * 8 + 4 + q4];
                bl[0] = Bl[n_][ks * 8 + q4];
                bl[1] = Bl[n_][ks * 8 + 4 + q4];
#pragma unroll
                for (int mt = 0; mt < 2; mt++) {
                    mma16816(acc[mt][nt], ah[mt], bh);
                    mma16816(acc[mt][nt], al[mt], bh);
                    mma16816(acc[mt][nt], ah[mt], bl);
                }
            }
        }
        __syncthreads();
    }

    // ---------------- epilogue ----------------
    if (epi == 0) {
#pragma unroll
        for (int mt = 0; mt < 2; mt++) {
            int rm0 = row0 + wm * 32 + mt * 16 + r;
            int rm1 = rm0 + 8;
#pragma unroll
            for (int nt = 0; nt < 8; nt++) {
                int cn = col0 + wn * 64 + nt * 8 + q4 * 2;
                if (rm0 < M) {
                    if (cn     < N) C[rm0 * ldc + cn]     = acc[mt][nt][0];
                    if (cn + 1 < N) C[rm0 * ldc + cn + 1] = acc[mt][nt][1];
                }
                if (rm1 < M) {
                    if (cn     < N) C[rm1 * ldc + cn]     = acc[mt][nt][2];
                    if (cn + 1 < N) C[rm1 * ldc + cn + 1] = acc[mt][nt][3];
                }
            }
        }
    } else {
        // attention scatter: rows are tokens, cols are d in [0,257)
        int h = z;
#pragma unroll
        for (int mt = 0; mt < 2; mt++) {
            int rm0 = row0 + wm * 32 + mt * 16 + r;
            int rm1 = rm0 + 8;
            float ds0 = 1.f, dh0 = 1.f, ds1 = 1.f, dh1 = 1.f;
            if (rm0 < M) { ds0 = dS[rm0 * HH + h] + 1e-6f; dh0 = dH[rm0 * HH + h] + 1e-8f; }
            if (rm1 < M) { ds1 = dS[rm1 * HH + h] + 1e-6f; dh1 = dH[rm1 * HH + h] + 1e-8f; }
#pragma unroll
            for (int nt = 0; nt < 8; nt++) {
                int cn = col0 + wn * 64 + nt * 8 + q4 * 2;
#pragma unroll
                for (int jj = 0; jj < 2; jj++) {
                    int d = cn + jj;
                    if (d >= DD) continue;
                    if (rm0 < M) {
                        float v = acc[mt][nt][jj];
                        if (d < SD) cs[rm0 * (HH * SD) + h * SD + d] = v / ds0;
                        else        ch[rm0 * (HH * OSD) + h * OSD + (d - SD)] = v / dh0;
                    }
                    if (rm1 < M) {
                        float v = acc[mt][nt][2 + jj];
                        if (d < SD) cs[rm1 * (HH * SD) + h * SD + d] = v / ds1;
                        else        ch[rm1 * (HH * OSD) + h * OSD + (d - SD)] = v / dh1;
                    }
                }
            }
        }
    }
}

// ---------------------------------------------------------------------------
// ktv (TN): ktvT[h][d][m] = sum_n Yk[n, h*257+m] * Yv[n, h*257+d]
// split-K over n with fp32 atomics; block-diagonal mask applied.
// blockIdx.x -> m tile, blockIdx.y -> d tile, blockIdx.z -> h * NSPLIT + split
// ---------------------------------------------------------------------------
#define KTV_NSPLIT 20
__global__ __launch_bounds__(256) void ktv_bf16s_tn(
    const float* __restrict__ Yk, const float* __restrict__ Yv,
    float* __restrict__ ktvT)
{
    __shared__ uint32_t Ah[128][20], Al[128][20], Bh[128][20], Bl[128][20];

    const int h  = blockIdx.z / KTV_NSPLIT;
    const int sp = blockIdx.z % KTV_NSPLIT;
    const int m0 = blockIdx.x * 128;
    const int d0 = blockIdx.y * 128;
    const int chunk = (NROWS + KTV_NSPLIT - 1) / KTV_NSPLIT;
    const int n0 = sp * chunk;
    int n1 = n0 + chunk; if (n1 > NROWS) n1 = NROWS;

    const float* Kp = Yk + h * DD;
    const float* Vp = Yv + h * DD;

    const int tid  = threadIdx.x;
    const int lane = tid & 31;
    const int wid  = tid >> 5;
    const int wm   = wid & 3;
    const int wn   = wid >> 2;
    const int r    = lane >> 2;
    const int q4   = lane & 3;

    float acc[2][8][4];
#pragma unroll
    for (int mt = 0; mt < 2; mt++)
#pragma unroll
        for (int nt = 0; nt < 8; nt++)
#pragma unroll
            for (int i = 0; i < 4; i++) acc[mt][nt][i] = 0.f;

    for (int kb = n0; kb < n1; kb += 32) {
        // A: 128 m-cols x 32 n-rows, transposed into smem [m][npair]
#pragma unroll
        for (int i = 0; i < 8; i++) {
            int idx = tid + i * 256;
            int m = idx & 127, np = idx >> 7;  // np 0..15
            int gm = m0 + m;
            int gn = kb + np * 2;
            bool mok = (gm < DD);
            float x0 = (mok && gn     < n1) ? __ldg(&Kp[gn * FF + gm])       : 0.f;
            float x1 = (mok && gn + 1 < n1) ? __ldg(&Kp[(gn + 1) * FF + gm]) : 0.f;
            uint32_t hp, lp; cvt_pack(x0, x1, hp, lp);
            Ah[m][np] = hp; Al[m][np] = lp;
        }
#pragma unroll
        for (int i = 0; i < 8; i++) {
            int idx = tid + i * 256;
            int d = idx & 127, np = idx >> 7;
            int gd = d0 + d;
            int gn = kb + np * 2;
            bool dok = (gd < DD);
            float x0 = (dok && gn     < n1) ? __ldg(&Vp[gn * FF + gd])       : 0.f;
            float x1 = (dok && gn + 1 < n1) ? __ldg(&Vp[(gn + 1) * FF + gd]) : 0.f;
            uint32_t hp, lp; cvt_pack(x0, x1, hp, lp);
            Bh[d][np] = hp; Bl[d][np] = lp;
        }
        __syncthreads();

#pragma unroll
        for (int ks = 0; ks < 2; ks++) {
            uint32_t ah[2][4], al[2][4];
#pragma unroll
            for (int mt = 0; mt < 2; mt++) {
                int m_ = wm * 32 + mt * 16;
                ah[mt][0] = Ah[m_ + r    ][ks * 8 + q4];
                ah[mt][1] = Ah[m_ + r + 8][ks * 8 + q4];
                ah[mt][2] = Ah[m_ + r    ][ks * 8 + 4 + q4];
                ah[mt][3] = Ah[m_ + r + 8][ks * 8 + 4 + q4];
                al[mt][0] = Al[m_ + r    ][ks * 8 + q4];
                al[mt][1] = Al[m_ + r + 8][ks * 8 + q4];
                al[mt][2] = Al[m_ + r    ][ks * 8 + 4 + q4];
                al[mt][3] = Al[m_ + r + 8][ks * 8 + 4 + q4];
            }
#pragma unroll
            for (int nt = 0; nt < 8; nt++) {
                int n_ = wn * 64 + nt * 8 + r;
                uint32_t bh[2], bl[2];
                bh[0] = Bh[n_][ks * 8 + q4];
                bh[1] = Bh[n_][ks * 8 + 4 + q4];
                bl[0] = Bl[n_][ks * 8 + q4];
                bl[1] = Bl[n_][ks * 8 + 4 + q4];
#pragma unroll
                for (int mt = 0; mt < 2; mt++) {
                    mma16816(acc[mt][nt], ah[mt], bh);
                    mma16816(acc[mt][nt], al[mt], bh);
                    mma16816(acc[mt][nt], ah[mt], bl);
                }
            }
        }
        __syncthreads();
    }

    float* kt = ktvT + h * DD * DD;
#pragma unroll
    for (int mt = 0; mt < 2; mt++) {
        int gm0 = m0 + wm * 32 + mt * 16 + r;
        int gm1 = gm0 + 8;
#pragma unroll
        for (int nt = 0; nt < 8; nt++) {
            int gd = d0 + wn * 64 + nt * 8 + q4 * 2;
#pragma unroll
            for (int jj = 0; jj < 2; jj++) {
                int d = gd + jj;
                if (d >= DD) continue;
                bool dside = (d < SD);
                if (gm0 < DD && ((gm0 < SD) == dside))
                    atomicAdd(&kt[d * DD + gm0], acc[mt][nt][jj]);
                if (gm1 < DD && ((gm1 < SD) == dside))
                    atomicAdd(&kt[d * DD + gm1], acc[mt][nt][2 + jj]);
            }
        }
    }
}

// --------- pseudo-linear epilogue: normalize first 17, optional phi --------
__global__ void ep1_kernel(float* __restrict__ Y, int do_phi)
{
    int warp = (blockIdx.x * blockDim.x + threadIdx.x) >> 5;
    int lane = threadIdx.x & 31;
    if (warp >= NROWS * HH) return;
    int n = warp / HH, h = warp % HH;
    float* p = Y + n * FF + h * DD;

    float x = (lane < SD) ? p[lane] : 0.f;
    float ss = x * x;
#pragma unroll
    for (int o = 16; o > 0; o >>= 1) ss += __shfl_xor_sync(0xffffffffu, ss, o);
    float scale = 1.f / (sqrtf(ss) + 1e-8f);
    if (lane < SD) {
        float y = x * scale;
        if (do_phi) y = (y > 0.f) ? y + 1.f : expf(y);
        p[lane] = y;
    }
    if (do_phi) {
        for (int j = SD + lane; j < DD; j += 32) {
            float y = p[j];
            p[j] = (y > 0.f) ? y + 1.f : expf(y);
        }
    }
}

__global__ void zero_kernel(float* __restrict__ p, int n)
{
    int i = blockIdx.x * blockDim.x + threadIdx.x;
    if (i < n) p[i] = 0.f;
}

// --------- column sums of phiK ---------------------------------------------
__global__ void colsum_kernel(const float* __restrict__ Y, float* __restrict__ out)
{
    int f = blockIdx.x * blockDim.x + threadIdx.x;
    if (f >= FF) return;
    int n0 = blockIdx.y * 750;
    int n1 = n0 + 750; if (n1 > NROWS) n1 = NROWS;
    float s = 0.f;
    for (int n = n0; n < n1; n++) s += Y[n * FF + f];
    atomicAdd(&out[f], s);
}

// --------- den_s / den_h per (n,h) -----------------------------------------
__global__ void den_kernel(const float* __restrict__ PQ,
                           const float* __restrict__ sumK,
                           float* __restrict__ dS, float* __restrict__ dH)
{
    int n = blockIdx.x;
    int h = threadIdx.x >> 5;
    int lane = threadIdx.x & 31;
    const float* p = PQ + n * FF + h * DD;
    const float* s = sumK + h * DD;
    float as = 0.f, ah = 0.f;
    for (int m = lane; m < DD; m += 32) {
        float v = p[m] * s[m];
        if (m < SD) as += v; else ah += v;
    }
#pragma unroll
    for (int o = 16; o > 0; o >>= 1) {
        as += __shfl_xor_sync(0xffffffffu, as, o);
        ah += __shfl_xor_sync(0xffffffffu, ah, o);
    }
    if (lane == 0) { dS[n * HH + h] = as; dH[n * HH + h] = ah; }
}

// --------- a = c_s @ Ws^T, then att_s = a / max(||a||, 1e-12) --------------
__global__ void a_kernel(const float* __restrict__ cs,
                         const float* __restrict__ Ws,
                         float* __restrict__ atts)
{
    __shared__ float ws[SD * 136];
    for (int i = threadIdx.x; i < SD * 136; i += blockDim.x) ws[i] = Ws[i];
    __syncthreads();
    int warp = threadIdx.x >> 5, lane = threadIdx.x & 31;
    int n = blockIdx.x * 8 + warp;
    if (n >= NROWS) return;
    float acc[SD];
#pragma unroll
    for (int o = 0; o < SD; o++) acc[o] = 0.f;
    for (int f = lane; f < 136; f += 32) {
        float x = cs[n * 136 + f];
#pragma unroll
        for (int o = 0; o < SD; o++) acc[o] += x * ws[o * 136 + f];
    }
#pragma unroll
    for (int o = 0; o < SD; o++)
#pragma unroll
        for (int s = 16; s > 0; s >>= 1)
            acc[o] += __shfl_xor_sync(0xffffffffu, acc[o], s);
    if (lane == 0) {
        float ss = 0.f;
#pragma unroll
        for (int o = 0; o < SD; o++) ss += acc[o] * acc[o];
        float sc = 1.f / fmaxf(sqrtf(ss), 1e-12f);
#pragma unroll
        for (int o = 0; o < SD; o++) atts[n * SD + o] = acc[o] * sc;
    }
}

// --------- final epilogue ---------------------------------------------------
__global__ void final_kernel(const float* __restrict__ b,
                             const float* __restrict__ atts,
                             float* __restrict__ out)
{
    int warp = threadIdx.x >> 5, lane = threadIdx.x & 31;
    int n = blockIdx.x * 8 + warp;
    if (n >= NROWS) return;
    const float* br = b + n * OSD;
    float ss = 0.f;
    for (int j = lane; j < OSD; j += 32) { float v = br[j]; ss += v * v; }
#pragma unroll
    for (int s = 16; s > 0; s >>= 1) ss += __shfl_xor_sync(0xffffffffu, ss, s);
    float nr  = sqrtf(ss);
    float bn  = nr + 1e-8f;
    float bnc = fminf(bn, 1e6f);
    float bt  = sqrtf(bnc * bnc + 1.0f);
    float scale = (bn > 1e6f) ? (1e6f / fmaxf(nr, 1e-12f * bnc)) : 1.0f;
    float* o = out + n * DD;
    for (int j = lane; j < OSD; j += 32) o[SD + j] = br[j] * scale;
    if (lane < SD) o[lane] = bt * atts[n * SD + lane];
}

// ---------------------------------------------------------------------------
extern "C" void kernel_launch(void* const* d_in, const int* in_sizes, int n_in,
                              void* d_out, int out_size)
{
    const float* qin = (const float*)d_in[0];
    const float* sin = (const float*)d_in[1];
    const float* Wq  = (const float*)d_in[2];
    const float* Wk  = (const float*)d_in[3];
    const float* Wv  = (const float*)d_in[4];
    const float* Ws  = (const float*)d_in[5];
    const float* Wh  = (const float*)d_in[6];
    float* out = (float*)d_out;

    float *Yq, *Yk, *Yv, *ktvT, *sumK, *dS, *dH, *cs, *ch, *atts, *bb;
    cudaGetSymbolAddress((void**)&Yq,   g_Yq);
    cudaGetSymbolAddress((void**)&Yk,   g_Yk);
    cudaGetSymbolAddress((void**)&Yv,   g_Yv);
    cudaGetSymbolAddress((void**)&ktvT, g_ktvT);
    cudaGetSymbolAddress((void**)&sumK, g_sumK);
    cudaGetSymbolAddress((void**)&dS,   g_denS);
    cudaGetSymbolAddress((void**)&dH,   g_denH);
    cudaGetSymbolAddress((void**)&cs,   g_cs);
    cudaGetSymbolAddress((void**)&ch,   g_ch);
    cudaGetSymbolAddress((void**)&atts, g_atts);
    cudaGetSymbolAddress((void**)&bb,   g_b);

    const int rowTiles = (NROWS + 127) / 128;   // 235
    const int fTiles   = (FF + 127) / 128;      // 17

    // 1. projections: Y = X @ W^T (tensor-core bf16 split)
    gemm_bf16s_nt<<<dim3(fTiles, rowTiles, 1), 256>>>(
        qin, Wq, Yq, NROWS, FF, DD, DD, DD, FF, 0, 0, 0, 0, nullptr, nullptr, nullptr, nullptr);
    gemm_bf16s_nt<<<dim3(fTiles, rowTiles, 1), 256>>>(
        sin, Wk, Yk, NROWS, FF, DD, DD, DD, FF, 0, 0, 0, 0, nullptr, nullptr, nullptr, nullptr);
    gemm_bf16s_nt<<<dim3(fTiles, rowTiles, 1), 256>>>(
        sin, Wv, Yv, NROWS, FF, DD, DD, DD, FF, 0, 0, 0, 0, nullptr, nullptr, nullptr, nullptr);

    // 2. pseudo-linear normalization + phi
    ep1_kernel<<<NROWS, 256>>>(Yq, 1);
    ep1_kernel<<<NROWS, 256>>>(Yk, 1);
    ep1_kernel<<<NROWS, 256>>>(Yv, 0);

    // 3. zero accumulators
    zero_kernel<<<(HH * DD * DD + 255) / 256, 256>>>(ktvT, HH * DD * DD);
    zero_kernel<<<(FF + 255) / 256, 256>>>(sumK, FF);

    // 4. sumK and ktvT (tensor-core TN with split-K atomics)
    colsum_kernel<<<dim3((FF + 255) / 256, 40), 256>>>(Yk, sumK);
    ktv_bf16s_tn<<<dim3(3, 3, HH * KTV_NSPLIT), 256>>>(Yk, Yv, ktvT);

    // 5. denominators
    den_kernel<<<NROWS, 256>>>(Yq, sumK, dS, dH);

    // 6. c = (phiQ @ ktv) / den, fused scatter into cs / ch
    gemm_bf16s_nt<<<dim3(3, rowTiles, HH), 256>>>(
        Yq, ktvT, nullptr, NROWS, DD, DD, FF, DD, 0, DD, DD * DD, 0,
        1, dS, dH, cs, ch);

    // 7. small Ws GEMM + att_s normalize
    a_kernel<<<(NROWS + 7) / 8, 256>>>(cs, Ws, atts);

    // 8. b = c_h @ Wh^T (tensor-core)
    gemm_bf16s_nt<<<dim3(2, rowTiles, 1), 256>>>(
        ch, Wh, bb, NROWS, OSD, HH * OSD, HH * OSD, HH * OSD, OSD,
        0, 0, 0, 0, nullptr, nullptr, nullptr, nullptr);

    // 9. final epilogue
    final_kernel<<<(NROWS + 7) / 8, 256>>>(bb, atts, out);
}

// round 3
// speedup vs baseline: 2.1062x; 1.0059x over previous
#include <cuda_runtime.h>
#include <cuda_bf16.h>
#include <stdint.h>
#include <math.h>

// Problem constants
#define NROWS 30000
#define HH    8
#define SD    17          // OT+1
#define OSD   240
#define DD    257         // IN_DIM == OUT_DIM
#define FF    2056        // H * 257

// ---------------- scratch (device globals; no runtime alloc allowed) -------
__device__ float g_Yq[NROWS * FF];      // phiQ after epilogue
__device__ float g_Yk[NROWS * FF];      // phiK after epilogue
__device__ float g_Yv[NROWS * FF];      // V after epilogue
__device__ float g_ktvT[HH * DD * DD];  // TRANSPOSED: ktvT[h][d][m]
__device__ float g_sumK[FF];
__device__ float g_denS[NROWS * HH];
__device__ float g_denH[NROWS * HH];
__device__ float g_cs[NROWS * HH * SD];   // N x 136
__device__ float g_ch[NROWS * HH * OSD];  // N x 1920
__device__ float g_atts[NROWS * SD];
__device__ float g_b[NROWS * OSD];

// ---------------------------------------------------------------------------
// helpers
// ---------------------------------------------------------------------------
__device__ __forceinline__ void mma16816(float c[4], const uint32_t a[4], const uint32_t b[2])
{
    asm volatile(
        "mma.sync.aligned.m16n8k16.row.col.f32.bf16.bf16.f32 "
        "{%0,%1,%2,%3}, {%4,%5,%6,%7}, {%8,%9}, {%0,%1,%2,%3};\n"
        : "+f"(c[0]), "+f"(c[1]), "+f"(c[2]), "+f"(c[3])
        : "r"(a[0]), "r"(a[1]), "r"(a[2]), "r"(a[3]), "r"(b[0]), "r"(b[1]));
}

__device__ __forceinline__ void cvt_pack(float x0, float x1, uint32_t& hp, uint32_t& lp)
{
    __nv_bfloat16 h0 = __float2bfloat16(x0);
    __nv_bfloat16 h1 = __float2bfloat16(x1);
    __nv_bfloat16 l0 = __float2bfloat16(x0 - __bfloat162float(h0));
    __nv_bfloat16 l1 = __float2bfloat16(x1 - __bfloat162float(h1));
    __nv_bfloat162 hh; hh.x = h0; hh.y = h1;
    __nv_bfloat162 ll; ll.x = l0; ll.y = l1;
    hp = *reinterpret_cast<uint32_t*>(&hh);
    lp = *reinterpret_cast<uint32_t*>(&ll);
}

// ---------------------------------------------------------------------------
// Generic NT tensor-core GEMM with bf16 hi/lo split:
//   C[m,n] = sum_k A[m,k]*B[n,k],  A,B,C fp32 in gmem.
// epi==0: plain store to C.
// epi==1: attention scatter: m=n-row, n=d; divide by den and write cs/ch.
// blockIdx.z selects batch (head); pointers advance by strides.
// ---------------------------------------------------------------------------
__global__ __launch_bounds__(256) void gemm_bf16s_nt(
    const float* __restrict__ A, const float* __restrict__ B, float* __restrict__ C,
    int M, int N, int K, int lda, int ldb, int ldc,
    int strideAz, int strideBz, int strideCz,
    int epi,
    const float* __restrict__ dS, const float* __restrict__ dH,
    float* __restrict__ cs, float* __restrict__ ch)
{
    __shared__ uint32_t Ah[128][20], Al[128][20], Bh[128][20], Bl[128][20];

    const int z = blockIdx.z;
    A += (long)z * strideAz;
    B += (long)z * strideBz;
    if (epi == 0) C += (long)z * strideCz;

    const int tid  = threadIdx.x;
    const int lane = tid & 31;
    const int wid  = tid >> 5;
    const int wm   = wid & 3;   // 4 warps along M (32 rows each)
    const int wn   = wid >> 2;  // 2 warps along N (64 cols each)
    const int row0 = blockIdx.y * 128;
    const int col0 = blockIdx.x * 128;
    const int r    = lane >> 2;
    const int q4   = lane & 3;

    float acc[2][8][4];
#pragma unroll
    for (int mt = 0; mt < 2; mt++)
#pragma unroll
        for (int nt = 0; nt < 8; nt++)
#pragma unroll
            for (int i = 0; i < 4; i++) acc[mt][nt][i] = 0.f;

    for (int k0 = 0; k0 < K; k0 += 32) {
        // fill A tile 128x32 (as 16 k-pairs)
#pragma unroll
        for (int i = 0; i < 8; i++) {
            int idx = tid + i * 256;
            int m = idx >> 4, kp = idx & 15;
            int gm = row0 + m, gk = k0 + kp * 2;
            float x0 = (gm < M && gk     < K) ? __ldg(&A[gm * lda + gk])     : 0.f;
            float x1 = (gm < M && gk + 1 < K) ? __ldg(&A[gm * lda + gk + 1]) : 0.f;
            uint32_t hp, lp; cvt_pack(x0, x1, hp, lp);
            Ah[m][kp] = hp; Al[m][kp] = lp;
        }
        // fill B tile 128x32
#pragma unroll
        for (int i = 0; i < 8; i++) {
            int idx = tid + i * 256;
            int n = idx >> 4, kp = idx & 15;
            int gn = col0 + n, gk = k0 + kp * 2;
            float x0 = (gn < N && gk     < K) ? __ldg(&B[gn * ldb + gk])     : 0.f;
            float x1 = (gn < N && gk + 1 < K) ? __ldg(&B[gn * ldb + gk + 1]) : 0.f;
            uint32_t hp, lp; cvt_pack(x0, x1, hp, lp);
            Bh[n][kp] = hp; Bl[n][kp] = lp;
        }
        __syncthreads();

#pragma unroll
        for (int ks = 0; ks < 2; ks++) {
            uint32_t ah[2][4], al[2][4];
#pragma unroll
            for (int mt = 0; mt < 2; mt++) {
                int m_ = wm * 32 + mt * 16;
                ah[mt][0] = Ah[m_ + r    ][ks * 8 + q4];
                ah[mt][1] = Ah[m_ + r + 8][ks * 8 + q4];
                ah[mt][2] = Ah[m_ + r    ][ks * 8 + 4 + q4];
                ah[mt][3] = Ah[m_ + r + 8][ks * 8 + 4 + q4];
                al[mt][0] = Al[m_ + r    ][ks * 8 + q4];
                al[mt][1] = Al[m_ + r + 8][ks * 8 + q4];
                al[mt][2] = Al[m_ + r    ][ks * 8 + 4 + q4];
                al[mt][3] = Al[m_ + r + 8][ks * 8 + 4 + q4];
            }
#pragma unroll
            for (int nt = 0; nt < 8; nt++) {
                int n_ = wn * 64 + nt * 8 + r;
                uint32_t bh[2], bl[2];
                bh[0] = Bh[n_][ks * 8 + q4];
                bh[1] = Bh[n_][ks * 8 + 4 + q4];
                bl[0] = Bl[n_][ks * 8 + q4];
                bl[1] = Bl[n_][ks * 8 + 4 + q4];
#pragma unroll
                for (int mt = 0; mt < 2; mt++) {
                    mma16816(acc[mt][nt], ah[mt], bh);
                    mma16816(acc[mt][nt], al[mt], bh);
                    mma16816(acc[mt][nt], ah[mt], bl);
                }
            }
        }
        __syncthreads();
    }

    // ---------------- epilogue ----------------
    if (epi == 0) {
#pragma unroll
        for (int mt = 0; mt < 2; mt++) {
            int rm0 = row0 + wm * 32 + mt * 16 + r;
            int rm1 = rm0 + 8;
#pragma unroll
            for (int nt = 0; nt < 8; nt++) {
                int cn = col0 + wn * 64 + nt * 8 + q4 * 2;
                if (rm0 < M) {
                    if (cn     < N) C[rm0 * ldc + cn]     = acc[mt][nt][0];
                    if (cn + 1 < N) C[rm0 * ldc + cn + 1] = acc[mt][nt][1];
                }
                if (rm1 < M) {
                    if (cn     < N) C[rm1 * ldc + cn]     = acc[mt][nt][2];
                    if (cn + 1 < N) C[rm1 * ldc + cn + 1] = acc[mt][nt][3];
                }
            }
        }
    } else {
        // attention scatter: rows are tokens, cols are d in [0,257)
        int h = z;
#pragma unroll
        for (int mt = 0; mt < 2; mt++) {
            int rm0 = row0 + wm * 32 + mt * 16 + r;
            int rm1 = rm0 + 8;
            float ds0 = 1.f, dh0 = 1.f, ds1 = 1.f, dh1 = 1.f;
            if (rm0 < M) { ds0 = dS[rm0 * HH + h] + 1e-6f; dh0 = dH[rm0 * HH + h] + 1e-8f; }
            if (rm1 < M) { ds1 = dS[rm1 * HH + h] + 1e-6f; dh1 = dH[rm1 * HH + h] + 1e-8f; }
#pragma unroll
            for (int nt = 0; nt < 8; nt++) {
                int cn = col0 + wn * 64 + nt * 8 + q4 * 2;
#pragma unroll
                for (int jj = 0; jj < 2; jj++) {
                    int d = cn + jj;
                    if (d >= DD) continue;
                    if (rm0 < M) {
                        float v = acc[mt][nt][jj];
                        if (d < SD) cs[rm0 * (HH * SD) + h * SD + d] = v / ds0;
                        else        ch[rm0 * (HH * OSD) + h * OSD + (d - SD)] = v / dh0;
                    }
                    if (rm1 < M) {
                        float v = acc[mt][nt][2 + jj];
                        if (d < SD) cs[rm1 * (HH * SD) + h * SD + d] = v / ds1;
                        else        ch[rm1 * (HH * OSD) + h * OSD + (d - SD)] = v / dh1;
                    }
                }
            }
        }
    }
}

// ---------------------------------------------------------------------------
// ktv (TN): ktvT[h][d][m] = sum_n Yk[n, h*257+m] * Yv[n, h*257+d]
// split-K over n with fp32 atomics; block-diagonal mask applied.
// blockIdx.x -> m tile, blockIdx.y -> d tile, blockIdx.z -> h * NSPLIT + split
// ---------------------------------------------------------------------------
#define KTV_NSPLIT 20
__global__ __launch_bounds__(256) void ktv_bf16s_tn(
    const float* __restrict__ Yk, const float* __restrict__ Yv,
    float* __restrict__ ktvT)
{
    __shared__ uint32_t Ah[128][20], Al[128][20], Bh[128][20], Bl[128][20];

    const int h  = blockIdx.z / KTV_NSPLIT;
    const int sp = blockIdx.z % KTV_NSPLIT;
    const int m0 = blockIdx.x * 128;
    const int d0 = blockIdx.y * 128;
    const int chunk = (NROWS + KTV_NSPLIT - 1) / KTV_NSPLIT;
    const int n0 = sp * chunk;
    int n1 = n0 + chunk; if (n1 > NROWS) n1 = NROWS;

    const float* Kp = Yk + h * DD;
    const float* Vp = Yv + h * DD;

    const int tid  = threadIdx.x;
    const int lane = tid & 31;
    const int wid  = tid >> 5;
    const int wm   = wid & 3;
    const int wn   = wid >> 2;
    const int r    = lane >> 2;
    const int q4   = lane & 3;

    float acc[2][8][4];
#pragma unroll
    for (int mt = 0; mt < 2; mt++)
#pragma unroll
        for (int nt = 0; nt < 8; nt++)
#pragma unroll
            for (int i = 0; i < 4; i++) acc[mt][nt][i] = 0.f;

    for (int kb = n0; kb < n1; kb += 32) {
        // A: 128 m-cols x 32 n-rows, transposed into smem [m][npair]
#pragma unroll
        for (int i = 0; i < 8; i++) {
            int idx = tid + i * 256;
            int m = idx & 127, np = idx >> 7;  // np 0..15
            int gm = m0 + m;
            int gn = kb + np * 2;
            bool mok = (gm < DD);
            float x0 = (mok && gn     < n1) ? __ldg(&Kp[gn * FF + gm])       : 0.f;
            float x1 = (mok && gn + 1 < n1) ? __ldg(&Kp[(gn + 1) * FF + gm]) : 0.f;
            uint32_t hp, lp; cvt_pack(x0, x1, hp, lp);
            Ah[m][np] = hp; Al[m][np] = lp;
        }
#pragma unroll
        for (int i = 0; i < 8; i++) {
            int idx = tid + i * 256;
            int d = idx & 127, np = idx >> 7;
            int gd = d0 + d;
            int gn = kb + np * 2;
            bool dok = (gd < DD);
            float x0 = (dok && gn     < n1) ? __ldg(&Vp[gn * FF + gd])       : 0.f;
            float x1 = (dok && gn + 1 < n1) ? __ldg(&Vp[(gn + 1) * FF + gd]) : 0.f;
            uint32_t hp, lp; cvt_pack(x0, x1, hp, lp);
            Bh[d][np] = hp; Bl[d][np] = lp;
        }
        __syncthreads();

#pragma unroll
        for (int ks = 0; ks < 2; ks++) {
            uint32_t ah[2][4], al[2][4];
#pragma unroll
            for (int mt = 0; mt < 2; mt++) {
                int m_ = wm * 32 + mt * 16;
                ah[mt][0] = Ah[m_ + r    ][ks * 8 + q4];
                ah[mt][1] = Ah[m_ + r + 8][ks * 8 + q4];
                ah[mt][2] = Ah[m_ + r    ][ks * 8 + 4 + q4];
                ah[mt][3] = Ah[m_ + r + 8][ks * 8 + 4 + q4];
                al[mt][0] = Al[m_ + r    ][ks * 8 + q4];
                al[mt][1] = Al[m_ + r + 8][ks * 8 + q4];
                al[mt][2] = Al[m_ + r    ][ks * 8 + 4 + q4];
                al[mt][3] = Al[m_ + r + 8][ks * 8 + 4 + q4];
            }
#pragma unroll
            for (int nt = 0; nt < 8; nt++) {
                int n_ = wn * 64 + nt * 8 + r;
                uint32_t bh[2], bl[2];
                bh[0] = Bh[n_][ks * 8 + q4];
                bh[1] = Bh[n_][ks * 8 + 4 + q4];
                bl[0] = Bl[n_][ks * 8 + q4];
                bl[1] = Bl[n_][ks * 8 + 4 + q4];
#pragma unroll
                for (int mt = 0; mt < 2; mt++) {
                    mma16816(acc[mt][nt], ah[mt], bh);
                    mma16816(acc[mt][nt], al[mt], bh);
                    mma16816(acc[mt][nt], ah[mt], bl);
                }
            }
        }
        __syncthreads();
    }

    float* kt = ktvT + h * DD * DD;
#pragma unroll
    for (int mt = 0; mt < 2; mt++) {
        int gm0 = m0 + wm * 32 + mt * 16 + r;
        int gm1 = gm0 + 8;
#pragma unroll
        for (int nt = 0; nt < 8; nt++) {
            int gd = d0 + wn * 64 + nt * 8 + q4 * 2;
#pragma unroll
            for (int jj = 0; jj < 2; jj++) {
                int d = gd + jj;
                if (d >= DD) continue;
                bool dside = (d < SD);
                if (gm0 < DD && ((gm0 < SD) == dside))
                    atomicAdd(&kt[d * DD + gm0], acc[mt][nt][jj]);
                if (gm1 < DD && ((gm1 < SD) == dside))
                    atomicAdd(&kt[d * DD + gm1], acc[mt][nt][2 + jj]);
            }
        }
    }
}

// --------- pseudo-linear epilogue: normalize first 17, optional phi --------
__global__ void ep1_kernel(float* __restrict__ Y, int do_phi)
{
    int warp = (blockIdx.x * blockDim.x + threadIdx.x) >> 5;
    int lane = threadIdx.x & 31;
    if (warp >= NROWS * HH) return;
    int n = warp / HH, h = warp % HH;
    float* p = Y + n * FF + h * DD;

    float x = (lane < SD) ? p[lane] : 0.f;
    float ss = x * x;
#pragma unroll
    for (int o = 16; o > 0; o >>= 1) ss += __shfl_xor_sync(0xffffffffu, ss, o);
    float scale = 1.f / (sqrtf(ss) + 1e-8f);
    if (lane < SD) {
        float y = x * scale;
        if (do_phi) y = (y > 0.f) ? y + 1.f : expf(y);
        p[lane] = y;
    }
    if (do_phi) {
        for (int j = SD + lane; j < DD; j += 32) {
            float y = p[j];
            p[j] = (y > 0.f) ? y + 1.f : expf(y);
        }
    }
}

__global__ void zero_kernel(float* __restrict__ p, int n)
{
    int i = blockIdx.x * blockDim.x + threadIdx.x;
    if (i < n) p[i] = 0.f;
}

// --------- column sums of phiK ---------------------------------------------
__global__ void colsum_kernel(const float* __restrict__ Y, float* __restrict__ out)
{
    int f = blockIdx.x * blockDim.x + threadIdx.x;
    if (f >= FF) return;
    int n0 = blockIdx.y * 750;
    int n1 = n0 + 750; if (n1 > NROWS) n1 = NROWS;
    float s = 0.f;
    for (int n = n0; n < n1; n++) s += Y[n * FF + f];
    atomicAdd(&out[f], s);
}

// --------- den_s / den_h per (n,h) -----------------------------------------
__global__ void den_kernel(const float* __restrict__ PQ,
                           const float* __restrict__ sumK,
                           float* __restrict__ dS, float* __restrict__ dH)
{
    int n = blockIdx.x;
    int h = threadIdx.x >> 5;
    int lane = threadIdx.x & 31;
    const float* p = PQ + n * FF + h * DD;
    const float* s = sumK + h * DD;
    float as = 0.f, ah = 0.f;
    for (int m = lane; m < DD; m += 32) {
        float v = p[m] * s[m];
        if (m < SD) as += v; else ah += v;
    }
#pragma unroll
    for (int o = 16; o > 0; o >>= 1) {
        as += __shfl_xor_sync(0xffffffffu, as, o);
        ah += __shfl_xor_sync(0xffffffffu, ah, o);
    }
    if (lane == 0) { dS[n * HH + h] = as; dH[n * HH + h] = ah; }
}

// --------- a = c_s @ Ws^T, then att_s = a / max(||a||, 1e-12) --------------
__global__ void a_kernel(const float* __restrict__ cs,
                         const float* __restrict__ Ws,
                         float* __restrict__ atts)
{
    __shared__ float ws[SD * 136];
    for (int i = threadIdx.x; i < SD * 136; i += blockDim.x) ws[i] = Ws[i];
    __syncthreads();
    int warp = threadIdx.x >> 5, lane = threadIdx.x & 31;
    int n = blockIdx.x * 8 + warp;
    if (n >= NROWS) return;
    float acc[SD];
#pragma unroll
    for (int o = 0; o < SD; o++) acc[o] = 0.f;
    for (int f = lane; f < 136; f += 32) {
        float x = cs[n * 136 + f];
#pragma unroll
        for (int o = 0; o < SD; o++) acc[o] += x * ws[o * 136 + f];
    }
#pragma unroll
    for (int o = 0; o < SD; o++)
#pragma unroll
        for (int s = 16; s > 0; s >>= 1)
            acc[o] += __shfl_xor_sync(0xffffffffu, acc[o], s);
    if (lane == 0) {
        float ss = 0.f;
#pragma unroll
        for (int o = 0; o < SD; o++) ss += acc[o] * acc[o];
        float sc = 1.f / fmaxf(sqrtf(ss), 1e-12f);
#pragma unroll
        for (int o = 0; o < SD; o++) atts[n * SD + o] = acc[o] * sc;
    }
}

// --------- final epilogue ---------------------------------------------------
__global__ void final_kernel(const float* __restrict__ b,
                             const float* __restrict__ atts,
                             float* __restrict__ out)
{
    int warp = threadIdx.x >> 5, lane = threadIdx.x & 31;
    int n = blockIdx.x * 8 + warp;
    if (n >= NROWS) return;
    const float* br = b + n * OSD;
    float ss = 0.f;
    for (int j = lane; j < OSD; j += 32) { float v = br[j]; ss += v * v; }
#pragma unroll
    for (int s = 16; s > 0; s >>= 1) ss += __shfl_xor_sync(0xffffffffu, ss, s);
    float nr  = sqrtf(ss);
    float bn  = nr + 1e-8f;
    float bnc = fminf(bn, 1e6f);
    float bt  = sqrtf(bnc * bnc + 1.0f);
    float scale = (bn > 1e6f) ? (1e6f / fmaxf(nr, 1e-12f * bnc)) : 1.0f;
    float* o = out + n * DD;
    for (int j = lane; j < OSD; j += 32) o[SD + j] = br[j] * scale;
    if (lane < SD) o[lane] = bt * atts[n * SD + lane];
}

// ---------------------------------------------------------------------------
extern "C" void kernel_launch(void* const* d_in, const int* in_sizes, int n_in,
                              void* d_out, int out_size)
{
    const float* qin = (const float*)d_in[0];
    const float* sin = (const float*)d_in[1];
    const float* Wq  = (const float*)d_in[2];
    const float* Wk  = (const float*)d_in[3];
    const float* Wv  = (const float*)d_in[4];
    const float* Ws  = (const float*)d_in[5];
    const float* Wh  = (const float*)d_in[6];
    float* out = (float*)d_out;

    float *Yq, *Yk, *Yv, *ktvT, *sumK, *dS, *dH, *cs, *ch, *atts, *bb;
    cudaGetSymbolAddress((void**)&Yq,   g_Yq);
    cudaGetSymbolAddress((void**)&Yk,   g_Yk);
    cudaGetSymbolAddress((void**)&Yv,   g_Yv);
    cudaGetSymbolAddress((void**)&ktvT, g_ktvT);
    cudaGetSymbolAddress((void**)&sumK, g_sumK);
    cudaGetSymbolAddress((void**)&dS,   g_denS);
    cudaGetSymbolAddress((void**)&dH,   g_denH);
    cudaGetSymbolAddress((void**)&cs,   g_cs);
    cudaGetSymbolAddress((void**)&ch,   g_ch);
    cudaGetSymbolAddress((void**)&atts, g_atts);
    cudaGetSymbolAddress((void**)&bb,   g_b);

    const int rowTiles = (NROWS + 127) / 128;   // 235
    const int fTiles   = (FF + 127) / 128;      // 17

    // 1. projections: Y = X @ W^T (tensor-core bf16 split)
    gemm_bf16s_nt<<<dim3(fTiles, rowTiles, 1), 256>>>(
        qin, Wq, Yq, NROWS, FF, DD, DD, DD, FF, 0, 0, 0, 0, nullptr, nullptr, nullptr, nullptr);
    gemm_bf16s_nt<<<dim3(fTiles, rowTiles, 1), 256>>>(
        sin, Wk, Yk, NROWS, FF, DD, DD, DD, FF, 0, 0, 0, 0, nullptr, nullptr, nullptr, nullptr);
    gemm_bf16s_nt<<<dim3(fTiles, rowTiles, 1), 256>>>(
        sin, Wv, Yv, NROWS, FF, DD, DD, DD, FF, 0, 0, 0, 0, nullptr, nullptr, nullptr, nullptr);

    // 2. pseudo-linear normalization + phi
    ep1_kernel<<<NROWS, 256>>>(Yq, 1);
    ep1_kernel<<<NROWS, 256>>>(Yk, 1);
    ep1_kernel<<<NROWS, 256>>>(Yv, 0);

    // 3. zero accumulators
    zero_kernel<<<(HH * DD * DD + 255) / 256, 256>>>(ktvT, HH * DD * DD);
    zero_kernel<<<(FF + 255) / 256, 256>>>(sumK, FF);

    // 4. sumK and ktvT (tensor-core TN with split-K atomics)
    colsum_kernel<<<dim3((FF + 255) / 256, 40), 256>>>(Yk, sumK);
    ktv_bf16s_tn<<<dim3(3, 3, HH * KTV_NSPLIT), 256>>>(Yk, Yv, ktvT);

    // 5. denominators
    den_kernel<<<NROWS, 256>>>(Yq, sumK, dS, dH);

    // 6. c = (phiQ @ ktv) / den, fused scatter into cs / ch
    gemm_bf16s_nt<<<dim3(3, rowTiles, HH), 256>>>(
        Yq, ktvT, nullptr, NROWS, DD, DD, FF, DD, 0, DD, DD * DD, 0,
        1, dS, dH, cs, ch);

    // 7. small Ws GEMM + att_s normalize
    a_kernel<<<(NROWS + 7) / 8, 256>>>(cs, Ws, atts);

    // 8. b = c_h @ Wh^T (tensor-core)
    gemm_bf16s_nt<<<dim3(2, rowTiles, 1), 256>>>(
        ch, Wh, bb, NROWS, OSD, HH * OSD, HH * OSD, HH * OSD, OSD,
        0, 0, 0, 0, nullptr, nullptr, nullptr, nullptr);

    // 9. final epilogue
    final_kernel<<<(NROWS + 7) / 8, 256>>>(bb, atts, out);
}